// round 16
// baseline (speedup 1.0000x reference)
#include <cuda_runtime.h>
#include <cuda_bf16.h>
#include <cstdint>
#include <cstddef>

#define NLOC   4096
#define NALL   6144
#define NDIM   128
#define EDIM   64
#define ADIM   32
#define NEDGE  262144
#define NANGLE 409600
#define INV_DYN_E 0.15625f            // 1/6.4
#define SYM_SCALE 0.0520833333333f    // (1/6.4)/3

// ---------------- device scratch ----------------
__device__ float g_sym[(size_t)NLOC * 768];
__device__ float g_base[(size_t)NLOC * 192];
__device__ float g_base2[(size_t)NALL * 192];
__device__ float g_nbase[(size_t)NLOC * 96];
__device__ float g_reduced[(size_t)NEDGE * EDIM];
__device__ float g_msg[(size_t)NLOC * NDIM];
__device__ int   g_ecnt[NLOC];
__device__ int   g_eoff[NLOC + 1];
__device__ int   g_ecur[NLOC];
__device__ int   g_eids[NEDGE];
__device__ int   g_enode[NEDGE];

// ---------------- helpers ----------------
__device__ __forceinline__ float silu_f(float x) { return x / (1.0f + __expf(-x)); }

__device__ __forceinline__ uint32_t smem_u32(const void* p) {
    uint32_t a;
    asm("{ .reg .u64 t; cvta.to.shared.u64 t, %1; cvt.u32.u64 %0, t; }" : "=r"(a) : "l"(p));
    return a;
}

__device__ __forceinline__ void ldsm4(uint32_t* r, uint32_t addr) {
    asm volatile("ldmatrix.sync.aligned.m8n8.x4.shared.b16 {%0,%1,%2,%3}, [%4];"
                 : "=r"(r[0]), "=r"(r[1]), "=r"(r[2]), "=r"(r[3]) : "r"(addr));
}
__device__ __forceinline__ void ldsm2(uint32_t* r, uint32_t addr) {
    asm volatile("ldmatrix.sync.aligned.m8n8.x2.shared.b16 {%0,%1}, [%2];"
                 : "=r"(r[0]), "=r"(r[1]) : "r"(addr));
}

__device__ __forceinline__ void mma_bf16(float* d, const uint32_t* a, const uint32_t* b) {
    asm volatile(
        "mma.sync.aligned.m16n8k16.row.col.f32.bf16.bf16.f32 "
        "{%0,%1,%2,%3}, {%4,%5,%6,%7}, {%8,%9}, {%0,%1,%2,%3};"
        : "+f"(d[0]), "+f"(d[1]), "+f"(d[2]), "+f"(d[3])
        : "r"(a[0]), "r"(a[1]), "r"(a[2]), "r"(a[3]), "r"(b[0]), "r"(b[1]));
}

__device__ __forceinline__ uint32_t bfp(float a, float b) {
    __nv_bfloat162 t = __floats2bfloat162_rn(a, b);
    return *reinterpret_cast<uint32_t*>(&t);
}

// ---------------- zero kernels ----------------
__global__ void k_init_small() {
    size_t i0 = (size_t)blockIdx.x * blockDim.x + threadIdx.x;
    size_t stride = (size_t)gridDim.x * blockDim.x;
    float4* m = reinterpret_cast<float4*>(g_msg);
    size_t m4 = (size_t)NLOC * NDIM / 4;
    for (size_t i = i0; i < m4; i += stride) m[i] = make_float4(0.f, 0.f, 0.f, 0.f);
    if (i0 < NLOC) g_ecnt[i0] = 0;
}

__global__ void k_zero_red() {
    size_t i0 = (size_t)blockIdx.x * blockDim.x + threadIdx.x;
    size_t stride = (size_t)gridDim.x * blockDim.x;
    float4* r = reinterpret_cast<float4*>(g_reduced);
    size_t n4 = (size_t)NEDGE * EDIM / 4;
    for (size_t i = i0; i < n4; i += stride) r[i] = make_float4(0.f, 0.f, 0.f, 0.f);
}

// ---------------- CSR build ----------------
__global__ void k_count(const int* __restrict__ n2e) {
    int e = blockIdx.x * blockDim.x + threadIdx.x;
    if (e < NEDGE) atomicAdd(&g_ecnt[n2e[e]], 1);
}

__global__ void k_scan() {
    __shared__ int sh[1024];
    int t = threadIdx.x;
    int c[4];
#pragma unroll
    for (int i = 0; i < 4; i++) c[i] = g_ecnt[t * 4 + i];
    int tot = c[0] + c[1] + c[2] + c[3];
    sh[t] = tot;
    __syncthreads();
    for (int st = 1; st < 1024; st <<= 1) {
        int add = (t >= st) ? sh[t - st] : 0;
        __syncthreads();
        sh[t] += add;
        __syncthreads();
    }
    int run = sh[t] - tot;
#pragma unroll
    for (int i = 0; i < 4; i++) {
        g_eoff[t * 4 + i] = run;
        g_ecur[t * 4 + i] = run;
        run += c[i];
    }
    if (t == 1023) g_eoff[NLOC] = run;
}

__global__ void k_scatter(const int* __restrict__ n2e) {
    int e = blockIdx.x * blockDim.x + threadIdx.x;
    if (e < NEDGE) {
        int n = n2e[e];
        int pos = atomicAdd(&g_ecur[n], 1);
        g_eids[pos] = e;
        g_enode[pos] = n;
    }
}

// ---------------- sym op: 4-way edge parallelism ----------------
__global__ __launch_bounds__(768) void k_sym(
    const float* __restrict__ edge_ebd, const float* __restrict__ node_ext,
    const float* __restrict__ h2, const float* __restrict__ sw,
    const int* __restrict__ n_ext2e) {
    __shared__ float P[4][3][192];
    __shared__ float S0[192], S1[192], S2[192];
    __shared__ float symv[768];
    int n = blockIdx.x;
    int t = threadIdx.x;
    int g = t / 192;
    int f = t - g * 192;
    int beg = g_eoff[n], end = g_eoff[n + 1];
    float a0 = 0.f, a1 = 0.f, a2 = 0.f;
    for (int i = beg + g; i < end; i += 4) {
        int e = g_eids[i];
        float swv = sw[e];
        float h0 = h2[e * 3 + 0] * swv;
        float h1 = h2[e * 3 + 1] * swv;
        float hh = h2[e * 3 + 2] * swv;
        float val = (f < 64) ? edge_ebd[(size_t)e * EDIM + f]
                             : node_ext[(size_t)n_ext2e[e] * NDIM + (f - 64)];
        a0 += h0 * val;
        a1 += h1 * val;
        a2 += hh * val;
    }
    P[g][0][f] = a0; P[g][1][f] = a1; P[g][2][f] = a2;
    __syncthreads();
    if (t < 192) {
        S0[t] = P[0][0][t] + P[1][0][t] + P[2][0][t] + P[3][0][t];
    } else if (t < 384) {
        int tt = t - 192;
        S1[tt] = P[0][1][tt] + P[1][1][tt] + P[2][1][tt] + P[3][1][tt];
    } else if (t < 576) {
        int tt = t - 384;
        S2[tt] = P[0][2][tt] + P[1][2][tt] + P[2][2][tt] + P[3][2][tt];
    }
    __syncthreads();
    if (t < 64) {
#pragma unroll
        for (int a = 0; a < 4; a++)
            symv[a * 64 + t] = SYM_SCALE * (S0[a] * S0[t] + S1[a] * S1[t] + S2[a] * S2[t]);
    } else if (t < 192) {
        int dn = t - 64;
#pragma unroll
        for (int a = 0; a < 4; a++)
            symv[256 + a * 128 + dn] =
                SYM_SCALE * (S0[64 + a] * S0[t] + S1[64 + a] * S1[t] + S2[64 + a] * S2[t]);
    }
    __syncthreads();
    g_sym[(size_t)n * 768 + t] = symv[t];
}

// ---------------- node_sym GEMM fused with node_self (M=32 tiles) ----------------
__global__ __launch_bounds__(256) void k_symmm(
    const float* __restrict__ W_sym, const float* __restrict__ b_sym,
    const float* __restrict__ n_res1,
    const float* __restrict__ W_self, const float* __restrict__ b_self,
    const float* __restrict__ n_res0,
    const float* __restrict__ node_ext, float* __restrict__ out_node) {
    __shared__ float Wt[32 * 128];
    __shared__ float At[32 * 36];
    int tid = threadIdx.x;
    int jt = tid & 31, mt = tid >> 5;
    int n0 = blockIdx.x * 32;
    float acc0[4][4], acc1[4][4];
#pragma unroll
    for (int i = 0; i < 4; i++)
#pragma unroll
        for (int q = 0; q < 4; q++) { acc0[i][q] = 0.f; acc1[i][q] = 0.f; }

    for (int kt = 0; kt < 768; kt += 32) {
        for (int idx = tid; idx < 32 * 128; idx += 256)
            Wt[idx] = W_sym[(size_t)(kt + idx / 128) * 128 + (idx % 128)];
        for (int idx = tid; idx < 32 * 32; idx += 256) {
            int m = idx / 32, k = idx % 32;
            At[k * 36 + m] = g_sym[(size_t)(n0 + m) * 768 + kt + k];
        }
        __syncthreads();
#pragma unroll 4
        for (int k = 0; k < 32; k++) {
            float4 A0 = *reinterpret_cast<const float4*>(&At[k * 36 + mt * 4]);
            float am[4] = {A0.x, A0.y, A0.z, A0.w};
            float4 wv = *reinterpret_cast<const float4*>(&Wt[k * 128 + jt * 4]);
            float wq[4] = {wv.x, wv.y, wv.z, wv.w};
#pragma unroll
            for (int i = 0; i < 4; i++)
#pragma unroll
                for (int q = 0; q < 4; q++) acc0[i][q] += am[i] * wq[q];
        }
        __syncthreads();
    }
    for (int kt = 0; kt < 128; kt += 32) {
        for (int idx = tid; idx < 32 * 128; idx += 256)
            Wt[idx] = W_self[(size_t)(kt + idx / 128) * 128 + (idx % 128)];
        for (int idx = tid; idx < 32 * 32; idx += 256) {
            int m = idx / 32, k = idx % 32;
            At[k * 36 + m] = node_ext[(size_t)(n0 + m) * NDIM + kt + k];
        }
        __syncthreads();
#pragma unroll 4
        for (int k = 0; k < 32; k++) {
            float4 A0 = *reinterpret_cast<const float4*>(&At[k * 36 + mt * 4]);
            float am[4] = {A0.x, A0.y, A0.z, A0.w};
            float4 wv = *reinterpret_cast<const float4*>(&Wt[k * 128 + jt * 4]);
            float wq[4] = {wv.x, wv.y, wv.z, wv.w};
#pragma unroll
            for (int i = 0; i < 4; i++)
#pragma unroll
                for (int q = 0; q < 4; q++) acc1[i][q] += am[i] * wq[q];
        }
        __syncthreads();
    }
#pragma unroll
    for (int i = 0; i < 4; i++) {
        int n = n0 + mt * 4 + i;
#pragma unroll
        for (int q = 0; q < 4; q++) {
            int j = jt * 4 + q;
            float y1 = silu_f(acc0[i][q] + b_sym[j]);
            float y0 = silu_f(acc1[i][q] + b_self[j]);
            out_node[(size_t)n * 128 + j] =
                node_ext[(size_t)n * NDIM + j] + n_res0[j] * y0 + n_res1[j] * y1;
        }
    }
}

// ---------------- fused base/base2 precompute ----------------
// blocks [0,64): g_base (W rows 0..127, +bias, NLOC)
// blocks [64,160): g_base2 (W rows 128..255, no bias, NALL)
__global__ __launch_bounds__(256) void k_bases(const float* __restrict__ node_ext,
                                               const float* __restrict__ W_ne,
                                               const float* __restrict__ W_es,
                                               const float* __restrict__ b_ne,
                                               const float* __restrict__ b_es) {
    __shared__ float Wt[32 * 192];
    __shared__ float At[32 * 72];
    int tid = threadIdx.x;
    int jt = tid & 31, mt = tid >> 5;
    bool role2 = (blockIdx.x >= 64);
    int n0 = (role2 ? (blockIdx.x - 64) : blockIdx.x) * 64;
    int rowbase = role2 ? 128 : 0;
    float acc[8][6];
#pragma unroll
    for (int i = 0; i < 8; i++)
#pragma unroll
        for (int c = 0; c < 6; c++) acc[i][c] = 0.f;
    for (int kt = 0; kt < 128; kt += 32) {
        for (int idx = tid; idx < 32 * 192; idx += 256) {
            int k = idx / 192, j = idx % 192;
            int row = rowbase + kt + k;
            Wt[idx] = (j < 128) ? W_ne[(size_t)row * 128 + j] : W_es[(size_t)row * 64 + (j - 128)];
        }
        for (int idx = tid; idx < 32 * 64; idx += 256) {
            int m = idx / 32, k = idx % 32;
            At[k * 72 + m] = node_ext[(size_t)(n0 + m) * NDIM + kt + k];
        }
        __syncthreads();
#pragma unroll 2
        for (int k = 0; k < 32; k++) {
            float4 A0 = *reinterpret_cast<const float4*>(&At[k * 72 + mt * 8]);
            float4 A1 = *reinterpret_cast<const float4*>(&At[k * 72 + mt * 8 + 4]);
            float am[8] = {A0.x, A0.y, A0.z, A0.w, A1.x, A1.y, A1.z, A1.w};
#pragma unroll
            for (int c = 0; c < 6; c++) {
                float w = Wt[k * 192 + jt + 32 * c];
#pragma unroll
                for (int i = 0; i < 8; i++) acc[i][c] += am[i] * w;
            }
        }
        __syncthreads();
    }
#pragma unroll
    for (int i = 0; i < 8; i++) {
        int n = n0 + mt * 8 + i;
#pragma unroll
        for (int c = 0; c < 6; c++) {
            int j = jt + 32 * c;
            if (role2) {
                g_base2[(size_t)n * 192 + j] = acc[i][c];
            } else {
                float bb = (j < 128) ? b_ne[j] : b_es[j - 128];
                g_base[(size_t)n * 192 + j] = acc[i][c] + bb;
            }
        }
    }
}

// ---------------- nbase precompute (angle kernel, 96 cols) ----------------
__global__ __launch_bounds__(256) void k_nbase(const float* __restrict__ node_ext,
                                               const float* __restrict__ W_ea1,
                                               const float* __restrict__ W_as,
                                               const float* __restrict__ b_ea1,
                                               const float* __restrict__ b_as) {
    __shared__ float Wt[32 * 96];
    __shared__ float At[32 * 72];
    int tid = threadIdx.x;
    int jt = tid & 31, mt = tid >> 5;
    int n0 = blockIdx.x * 64;
    float acc[8][3];
#pragma unroll
    for (int i = 0; i < 8; i++)
#pragma unroll
        for (int c = 0; c < 3; c++) acc[i][c] = 0.f;
    for (int kt = 0; kt < 128; kt += 32) {
        for (int idx = tid; idx < 32 * 96; idx += 256) {
            int k = idx / 96, j = idx % 96;
            int row = 32 + kt + k;
            Wt[idx] = (j < 64) ? W_ea1[(size_t)row * 64 + j] : W_as[(size_t)row * 32 + (j - 64)];
        }
        for (int idx = tid; idx < 32 * 64; idx += 256) {
            int m = idx / 32, k = idx % 32;
            At[k * 72 + m] = node_ext[(size_t)(n0 + m) * NDIM + kt + k];
        }
        __syncthreads();
#pragma unroll 2
        for (int k = 0; k < 32; k++) {
            float4 A0 = *reinterpret_cast<const float4*>(&At[k * 72 + mt * 8]);
            float4 A1 = *reinterpret_cast<const float4*>(&At[k * 72 + mt * 8 + 4]);
            float am[8] = {A0.x, A0.y, A0.z, A0.w, A1.x, A1.y, A1.z, A1.w};
#pragma unroll
            for (int c = 0; c < 3; c++) {
                float w = Wt[k * 96 + jt + 32 * c];
#pragma unroll
                for (int i = 0; i < 8; i++) acc[i][c] += am[i] * w;
            }
        }
        __syncthreads();
    }
#pragma unroll
    for (int i = 0; i < 8; i++) {
        int n = n0 + mt * 8 + i;
#pragma unroll
        for (int c = 0; c < 3; c++) {
            int j = jt + 32 * c;
            float bb = (j < 64) ? b_ea1[j] : b_as[j - 64];
            g_nbase[(size_t)n * 96 + j] = acc[i][c] + bb;
        }
    }
}

// ================= edge GEMM via mma.sync bf16 1-term =================
#define ET_WH 0
#define ET_AH 27648
#define ET_IDX 36864
#define ET_SMEM 37888

__global__ __launch_bounds__(512, 2) void k_edge_tc(
    const float* __restrict__ edge_ebd,
    const float* __restrict__ sw, const int* __restrict__ n_ext2e,
    const float* __restrict__ W_ne, const float* __restrict__ W_es,
    const float* __restrict__ e_res0, float* __restrict__ out_edge) {
    extern __shared__ char smc[];
    uint32_t sb = smem_u32(smc);
    int tid = threadIdx.x;
    int wid = tid >> 5;
    int lane = tid & 31;
    int wm = wid >> 2;
    int wn = wid & 3;

    int* eidv = (int*)(smc + ET_IDX);
    int* nodev = eidv + 64;
    int* neiv = nodev + 64;
    float* sws = (float*)(neiv + 64);

    for (int idx = tid; idx < 192 * 64; idx += 512) {
        int j = idx / 64, k = idx % 64;
        int row = 256 + k;
        float w = (j < 128) ? W_ne[(size_t)row * 128 + j] : W_es[(size_t)row * 64 + (j - 128)];
        *reinterpret_cast<__nv_bfloat16*>(smc + ET_WH + (j * 72 + k) * 2) = __float2bfloat16(w);
    }

    uint32_t aRow = wm * 16 + (lane & 15);
    uint32_t aColH = (lane >> 4);
    uint32_t aAddrH = sb + ET_AH + (aRow * 72 + aColH * 8) * 2;
    int nrow = wn * 48 + (lane & 7) + ((lane & 16) ? 8 : 0);
    int khalf = (lane & 8) ? 8 : 0;
    uint32_t bAddrH = sb + ET_WH + (nrow * 72 + khalf) * 2;

    int mfill = tid & 63;
    int seg = tid >> 6;

    for (int ch = blockIdx.x; ch < NEDGE / 64; ch += gridDim.x) {
        int c0 = ch * 64;
        __syncthreads();
        if (tid < 64) {
            int e = g_eids[c0 + tid];
            eidv[tid] = e;
            nodev[tid] = g_enode[c0 + tid];
            neiv[tid] = n_ext2e[e];
            sws[tid] = sw[e];
        }
        {
            int e = __ldg(&g_eids[c0 + mfill]);
            const float4* erowp = (const float4*)(edge_ebd + (size_t)e * EDIM);
            uint32_t rowoff = (uint32_t)mfill * 72;
#pragma unroll
            for (int q = 0; q < 2; q++) {
                int kk = seg * 8 + q * 4;
                float4 v = erowp[kk >> 2];
                uint32_t hi01 = bfp(v.x, v.y);
                uint32_t hi23 = bfp(v.z, v.w);
                uint32_t boff = (rowoff + kk) * 2;
                *reinterpret_cast<uint32_t*>(smc + ET_AH + boff) = hi01;
                *reinterpret_cast<uint32_t*>(smc + ET_AH + boff + 4) = hi23;
            }
        }
        __syncthreads();

        float d[6][4];
#pragma unroll
        for (int nt = 0; nt < 6; nt++)
#pragma unroll
            for (int q = 0; q < 4; q++) d[nt][q] = 0.f;

#pragma unroll
        for (int s = 0; s < 4; s++) {
            uint32_t ah[4];
            ldsm4(ah, aAddrH + s * 32);
#pragma unroll
            for (int pr = 0; pr < 3; pr++) {
                uint32_t bh[4];
                ldsm4(bh, bAddrH + pr * 16 * 144 + s * 32);
                mma_bf16(d[pr * 2], ah, bh);
                mma_bf16(d[pr * 2 + 1], ah, bh + 2);
            }
        }

        int g = lane >> 2, qt = lane & 3;
        int r0 = wm * 16 + g, r1 = r0 + 8;
        int nd0 = nodev[r0], nd1 = nodev[r1];
        int ne0 = neiv[r0], ne1 = neiv[r1];
        float sw0 = sws[r0], sw1 = sws[r1];
        int ee0 = eidv[r0], ee1 = eidv[r1];
        bool samend = (nd0 == nd1);
#pragma unroll
        for (int nt = 0; nt < 6; nt++) {
            int j0 = wn * 48 + nt * 8 + qt * 2;
            float2 b0v = *(const float2*)(g_base + (size_t)nd0 * 192 + j0);
            float2 b1v = *(const float2*)(g_base + (size_t)nd1 * 192 + j0);
            float2 c0v = *(const float2*)(g_base2 + (size_t)ne0 * 192 + j0);
            float2 c1v = *(const float2*)(g_base2 + (size_t)ne1 * 192 + j0);
            float y00 = silu_f(d[nt][0] + b0v.x + c0v.x);
            float y01 = silu_f(d[nt][1] + b0v.y + c0v.y);
            float y10 = silu_f(d[nt][2] + b1v.x + c1v.x);
            float y11 = silu_f(d[nt][3] + b1v.y + c1v.y);
            if (j0 < 128) {
                float v00 = y00 * sw0, v01 = y01 * sw0;
                float v10 = y10 * sw1, v11 = y11 * sw1;
                if (samend) {
                    atomicAdd(&g_msg[(size_t)nd0 * NDIM + j0], v00 + v10);
                    atomicAdd(&g_msg[(size_t)nd0 * NDIM + j0 + 1], v01 + v11);
                } else {
                    atomicAdd(&g_msg[(size_t)nd0 * NDIM + j0], v00);
                    atomicAdd(&g_msg[(size_t)nd0 * NDIM + j0 + 1], v01);
                    atomicAdd(&g_msg[(size_t)nd1 * NDIM + j0], v10);
                    atomicAdd(&g_msg[(size_t)nd1 * NDIM + j0 + 1], v11);
                }
            } else {
                int col = j0 - 128;
                float2 er = *(const float2*)(e_res0 + col);
                size_t o0 = (size_t)ee0 * EDIM + col;
                size_t o1 = (size_t)ee1 * EDIM + col;
                float2 eb0 = *(const float2*)(edge_ebd + o0);
                float2 eb1 = *(const float2*)(edge_ebd + o1);
                *(float2*)(out_edge + o0) = make_float2(eb0.x + er.x * y00, eb0.y + er.y * y01);
                *(float2*)(out_edge + o1) = make_float2(eb1.x + er.x * y10, eb1.y + er.y * y11);
            }
        }
    }
}

// ================= angle GEMM via mma.sync bf16 1-term =================
#define AT_WH 0
#define AT_AH 32256
#define AT_IDX 53760
#define AT_SMEM 54528

__global__ __launch_bounds__(512, 2) void k_angle_tc(
    const float* __restrict__ angle_ebd, const float* __restrict__ edge_ebd,
    const int* __restrict__ ai, const float* __restrict__ a_sw,
    const float* __restrict__ W_ea1, const float* __restrict__ W_as,
    const float* __restrict__ a_res0, float* __restrict__ out_angle) {
    extern __shared__ char smc[];
    uint32_t sb = smem_u32(smc);
    int tid = threadIdx.x;
    int wid = tid >> 5;
    int lane = tid & 31;
    int wm = wid >> 2;
    int wn = wid & 3;

    int* nav = (int*)(smc + AT_IDX);
    int* ijav = nav + 64;
    float* aswv = (float*)(ijav + 64);

    const int* n2a = ai;
    const int* eij = ai + NANGLE;
    const int* eik = ai + 2 * NANGLE;

    for (int idx = tid; idx < 96 * 160; idx += 512) {
        int j = idx / 160, k = idx % 160;
        int srck = (k < 32) ? k : ((k < 96) ? 160 + (k - 32) : 224 + (k - 96));
        float w = (j < 64) ? W_ea1[(size_t)srck * 64 + j] : W_as[(size_t)srck * 32 + (j - 64)];
        *reinterpret_cast<__nv_bfloat16*>(smc + AT_WH + (j * 168 + k) * 2) = __float2bfloat16(w);
    }

    uint32_t aRow = wm * 16 + (lane & 15);
    uint32_t aColH = (lane >> 4);
    uint32_t aAddrH = sb + AT_AH + (aRow * 168 + aColH * 8) * 2;
    int nrow = wn * 24 + (lane & 7) + ((lane & 16) ? 8 : 0);
    int khalf = (lane & 8) ? 8 : 0;
    uint32_t bAddrH = sb + AT_WH + (nrow * 168 + khalf) * 2;
    int nrow2 = wn * 24 + 16 + (lane & 7);
    int khalf2 = (lane & 8) ? 8 : 0;
    uint32_t b2AddrH = sb + AT_WH + (nrow2 * 168 + khalf2) * 2;

    int mfill = tid & 63;
    int seg = tid >> 6;

    for (int t = blockIdx.x; t < NANGLE / 64; t += gridDim.x) {
        int a0 = t * 64;
        __syncthreads();
        if (tid < 64) {
            nav[tid] = n2a[a0 + tid];
            ijav[tid] = eij[a0 + tid];
            aswv[tid] = a_sw[a0 + tid];
        }
        {
            int a = a0 + mfill;
            int ek = __ldg(&eik[a]);
            int ej = __ldg(&eij[a]);
            const float4* arow = (const float4*)(angle_ebd + (size_t)a * ADIM);
            const float4* krow = (const float4*)(edge_ebd + (size_t)ek * EDIM);
            const float4* jrow = (const float4*)(edge_ebd + (size_t)ej * EDIM);
            uint32_t rowoff = (uint32_t)mfill * 168;
#pragma unroll
            for (int q = 0; q < 5; q++) {
                int kk = seg * 20 + q * 4;
                float4 v = (kk < 32) ? arow[kk >> 2]
                         : (kk < 96) ? krow[(kk - 32) >> 2]
                                     : jrow[(kk - 96) >> 2];
                uint32_t hi01 = bfp(v.x, v.y);
                uint32_t hi23 = bfp(v.z, v.w);
                uint32_t boff = (rowoff + kk) * 2;
                *reinterpret_cast<uint32_t*>(smc + AT_AH + boff) = hi01;
                *reinterpret_cast<uint32_t*>(smc + AT_AH + boff + 4) = hi23;
            }
        }
        __syncthreads();

        float d[3][4];
#pragma unroll
        for (int nt = 0; nt < 3; nt++)
#pragma unroll
            for (int q = 0; q < 4; q++) d[nt][q] = 0.f;

#pragma unroll
        for (int s = 0; s < 10; s++) {
            uint32_t ah[4];
            ldsm4(ah, aAddrH + s * 32);
            uint32_t bh[4], b2h[2];
            ldsm4(bh, bAddrH + s * 32);
            ldsm2(b2h, b2AddrH + s * 32);
            mma_bf16(d[0], ah, bh);
            mma_bf16(d[1], ah, bh + 2);
            mma_bf16(d[2], ah, b2h);
        }

        int g = lane >> 2, qt = lane & 3;
        int r0 = wm * 16 + g, r1 = r0 + 8;
        int nd0 = nav[r0], nd1 = nav[r1];
        float sw0 = aswv[r0], sw1 = aswv[r1];
        int ij0 = ijav[r0], ij1 = ijav[r1];
#pragma unroll
        for (int nt = 0; nt < 3; nt++) {
            int j0 = wn * 24 + nt * 8 + qt * 2;
            float2 nb0 = *(const float2*)(g_nbase + (size_t)nd0 * 96 + j0);
            float2 nb1 = *(const float2*)(g_nbase + (size_t)nd1 * 96 + j0);
            float y00 = silu_f(d[nt][0] + nb0.x);
            float y01 = silu_f(d[nt][1] + nb0.y);
            float y10 = silu_f(d[nt][2] + nb1.x);
            float y11 = silu_f(d[nt][3] + nb1.y);
            if (j0 < 64) {
                atomicAdd(&g_reduced[(size_t)ij0 * EDIM + j0], y00 * sw0);
                atomicAdd(&g_reduced[(size_t)ij0 * EDIM + j0 + 1], y01 * sw0);
                atomicAdd(&g_reduced[(size_t)ij1 * EDIM + j0], y10 * sw1);
                atomicAdd(&g_reduced[(size_t)ij1 * EDIM + j0 + 1], y11 * sw1);
            } else {
                int col = j0 - 64;
                float2 arr = *(const float2*)(a_res0 + col);
                size_t o0 = (size_t)(a0 + r0) * ADIM + col;
                size_t o1 = (size_t)(a0 + r1) * ADIM + col;
                float2 ae0 = *(const float2*)(angle_ebd + o0);
                float2 ae1 = *(const float2*)(angle_ebd + o1);
                *(float2*)(out_angle + o0) = make_float2(ae0.x + arr.x * y00, ae0.y + arr.y * y01);
                *(float2*)(out_angle + o1) = make_float2(ae1.x + arr.x * y10, ae1.y + arr.y * y11);
            }
        }
    }
}

// ================= edge angle message GEMM (+ node finish blocks) =================
__global__ __launch_bounds__(256) void k_edge_msg(const float* __restrict__ W2,
                                                  const float* __restrict__ b2,
                                                  const float* __restrict__ e_res1,
                                                  float* __restrict__ out_edge,
                                                  const float* __restrict__ n_res2,
                                                  float* __restrict__ out_node) {
    int tid = threadIdx.x;
    if (blockIdx.x >= NEDGE / 64) {
        // node finish role
        int i0 = (blockIdx.x - NEDGE / 64) * 256 + tid;
        for (int i = i0; i < NLOC * NDIM; i += 64 * 256) {
            int j = i & (NDIM - 1);
            out_node[i] += n_res2[j] * g_msg[i] * INV_DYN_E;
        }
        return;
    }
    __shared__ __align__(16) __nv_bfloat16 Wh[64 * 72];
    __shared__ __align__(16) __nv_bfloat16 Ah[64 * 72];
    int wid = tid >> 5;
    int lane = tid & 31;
    int wm = wid >> 1;
    int wn = wid & 1;
    int e0 = blockIdx.x * 64;

    for (int idx = tid; idx < 64 * 64; idx += 256) {
        int j = idx >> 6, k = idx & 63;
        Wh[j * 72 + k] = __float2bfloat16(W2[k * 64 + j]);
    }
    {
        int m = tid & 63, seg = tid >> 6;
        const float4* src = (const float4*)(g_reduced + (size_t)(e0 + m) * EDIM + seg * 16);
#pragma unroll
        for (int q = 0; q < 4; q++) {
            float4 v = src[q];
            int kk = seg * 16 + q * 4;
            Ah[m * 72 + kk + 0] = __float2bfloat16(v.x);
            Ah[m * 72 + kk + 1] = __float2bfloat16(v.y);
            Ah[m * 72 + kk + 2] = __float2bfloat16(v.z);
            Ah[m * 72 + kk + 3] = __float2bfloat16(v.w);
        }
    }
    __syncthreads();

    uint32_t aRow = wm * 16 + (lane & 15);
    uint32_t aColH = (lane >> 4);
    uint32_t aAddrH = smem_u32(Ah) + (aRow * 72 + aColH * 8) * 2;
    int nrow = wn * 32 + (lane & 7) + ((lane & 16) ? 8 : 0);
    int khalf = (lane & 8) ? 8 : 0;
    uint32_t bAddrH = smem_u32(Wh) + (nrow * 72 + khalf) * 2;
    uint32_t b2AddrH = bAddrH + 16 * 144;

    float d[4][4];
#pragma unroll
    for (int nt = 0; nt < 4; nt++)
#pragma unroll
        for (int q = 0; q < 4; q++) d[nt][q] = 0.f;

#pragma unroll
    for (int s = 0; s < 4; s++) {
        uint32_t ah[4];
        ldsm4(ah, aAddrH + s * 32);
        uint32_t bh[4], ch[4];
        ldsm4(bh, bAddrH + s * 32);
        ldsm4(ch, b2AddrH + s * 32);
        mma_bf16(d[0], ah, bh);
        mma_bf16(d[1], ah, bh + 2);
        mma_bf16(d[2], ah, ch);
        mma_bf16(d[3], ah, ch + 2);
    }

    int g = lane >> 2, qt = lane & 3;
    int r0 = wm * 16 + g, r1 = r0 + 8;
#pragma unroll
    for (int nt = 0; nt < 4; nt++) {
        int j0 = wn * 32 + nt * 8 + qt * 2;
        float2 bb = *(const float2*)(b2 + j0);
        float2 er = *(const float2*)(e_res1 + j0);
        size_t o0 = (size_t)(e0 + r0) * EDIM + j0;
        size_t o1 = (size_t)(e0 + r1) * EDIM + j0;
        float2 v0 = *(float2*)(out_edge + o0);
        float2 v1 = *(float2*)(out_edge + o1);
        v0.x += er.x * silu_f(d[nt][0] + bb.x);
        v0.y += er.y * silu_f(d[nt][1] + bb.y);
        v1.x += er.x * silu_f(d[nt][2] + bb.x);
        v1.y += er.y * silu_f(d[nt][3] + bb.y);
        *(float2*)(out_edge + o0) = v0;
        *(float2*)(out_edge + o1) = v1;
    }
}

// ---------------- launch ----------------
extern "C" void kernel_launch(void* const* d_in, const int* in_sizes, int n_in,
                              void* d_out, int out_size) {
    const float* node_ext   = (const float*)d_in[0];
    const float* edge_ebd   = (const float*)d_in[1];
    const float* h2         = (const float*)d_in[2];
    const float* angle_ebd  = (const float*)d_in[3];
    const float* sw         = (const float*)d_in[6];
    const float* a_sw       = (const float*)d_in[9];
    const int*   edge_index = (const int*)d_in[10];
    const int*   angle_index= (const int*)d_in[11];
    const float* W_node_self = (const float*)d_in[12];
    const float* b_node_self = (const float*)d_in[13];
    const float* W_node_sym  = (const float*)d_in[14];
    const float* b_node_sym  = (const float*)d_in[15];
    const float* W_node_edge = (const float*)d_in[16];
    const float* b_node_edge = (const float*)d_in[17];
    const float* W_edge_self = (const float*)d_in[18];
    const float* b_edge_self = (const float*)d_in[19];
    const float* W_edge_angle1 = (const float*)d_in[20];
    const float* b_edge_angle1 = (const float*)d_in[21];
    const float* W_edge_angle2 = (const float*)d_in[22];
    const float* b_edge_angle2 = (const float*)d_in[23];
    const float* W_angle_self  = (const float*)d_in[24];
    const float* b_angle_self  = (const float*)d_in[25];
    const float* n_res0 = (const float*)d_in[26];
    const float* n_res1 = (const float*)d_in[27];
    const float* n_res2 = (const float*)d_in[28];
    const float* e_res0 = (const float*)d_in[29];
    const float* e_res1 = (const float*)d_in[30];
    const float* a_res0 = (const float*)d_in[31];

    float* out = (float*)d_out;
    float* out_node  = out;
    float* out_edge  = out + (size_t)NLOC * NDIM;
    float* out_angle = out_edge + (size_t)NEDGE * EDIM;

    const int* n2e = edge_index;
    const int* n_ext2e = edge_index + NEDGE;

    cudaFuncSetAttribute((const void*)k_edge_tc,
                         cudaFuncAttributeMaxDynamicSharedMemorySize, ET_SMEM);
    cudaFuncSetAttribute((const void*)k_angle_tc,
                         cudaFuncAttributeMaxDynamicSharedMemorySize, AT_SMEM);

    // fork a side stream for the angle-independent chain
    cudaStream_t s2;
    cudaStreamCreateWithFlags(&s2, cudaStreamNonBlocking);
    cudaEvent_t ev_fork, ev_join;
    cudaEventCreateWithFlags(&ev_fork, cudaEventDisableTiming);
    cudaEventCreateWithFlags(&ev_join, cudaEventDisableTiming);

    cudaEventRecord(ev_fork, 0);
    cudaStreamWaitEvent(s2, ev_fork, 0);

    // side chain: zero g_reduced -> nbase -> angle_tc
    k_zero_red<<<4096, 256, 0, s2>>>();
    k_nbase<<<NLOC / 64, 256, 0, s2>>>(node_ext, W_edge_angle1, W_angle_self,
                                       b_edge_angle1, b_angle_self);
    k_angle_tc<<<296, 512, AT_SMEM, s2>>>(angle_ebd, edge_ebd, angle_index, a_sw,
                                          W_edge_angle1, W_angle_self, a_res0, out_angle);
    cudaEventRecord(ev_join, s2);

    // main chain
    k_init_small<<<2048, 256>>>();
    k_count<<<NEDGE / 256, 256>>>(n2e);
    k_scan<<<1, 1024>>>();
    k_scatter<<<NEDGE / 256, 256>>>(n2e);
    k_sym<<<NLOC, 768>>>(edge_ebd, node_ext, h2, sw, n_ext2e);
    k_symmm<<<NLOC / 32, 256>>>(W_node_sym, b_node_sym, n_res1,
                                W_node_self, b_node_self, n_res0, node_ext, out_node);
    k_bases<<<160, 256>>>(node_ext, W_node_edge, W_edge_self, b_node_edge, b_edge_self);
    k_edge_tc<<<296, 512, ET_SMEM>>>(edge_ebd, sw, n_ext2e,
                                     W_node_edge, W_edge_self, e_res0, out_edge);

    // join, then final edge update + node finish
    cudaStreamWaitEvent(0, ev_join, 0);
    k_edge_msg<<<NEDGE / 64 + 64, 256>>>(W_edge_angle2, b_edge_angle2, e_res1, out_edge,
                                         n_res2, out_node);

    cudaEventDestroy(ev_fork);
    cudaEventDestroy(ev_join);
    cudaStreamDestroy(s2);
}

// round 17
// speedup vs baseline: 1.0322x; 1.0322x over previous
#include <cuda_runtime.h>
#include <cuda_bf16.h>
#include <cstdint>
#include <cstddef>

#define NLOC   4096
#define NALL   6144
#define NDIM   128
#define EDIM   64
#define ADIM   32
#define NEDGE  262144
#define NANGLE 409600
#define INV_DYN_E 0.15625f            // 1/6.4
#define SYM_SCALE 0.0520833333333f    // (1/6.4)/3

// ---------------- device scratch ----------------
__device__ float g_sym[(size_t)NLOC * 768];
__device__ float g_base[(size_t)NLOC * 192];
__device__ float g_base2[(size_t)NALL * 192];
__device__ float g_nbase[(size_t)NLOC * 96];
__device__ float g_reduced[(size_t)NEDGE * EDIM];
__device__ float g_msg[(size_t)NLOC * NDIM];
__device__ int   g_ecnt[NLOC];
__device__ int   g_eoff[NLOC + 1];
__device__ int   g_ecur[NLOC];
__device__ int   g_eids[NEDGE];
__device__ int   g_enode[NEDGE];

// ---------------- helpers ----------------
__device__ __forceinline__ float silu_f(float x) { return x / (1.0f + __expf(-x)); }

__device__ __forceinline__ uint32_t smem_u32(const void* p) {
    uint32_t a;
    asm("{ .reg .u64 t; cvta.to.shared.u64 t, %1; cvt.u32.u64 %0, t; }" : "=r"(a) : "l"(p));
    return a;
}

__device__ __forceinline__ void ldsm4(uint32_t* r, uint32_t addr) {
    asm volatile("ldmatrix.sync.aligned.m8n8.x4.shared.b16 {%0,%1,%2,%3}, [%4];"
                 : "=r"(r[0]), "=r"(r[1]), "=r"(r[2]), "=r"(r[3]) : "r"(addr));
}
__device__ __forceinline__ void ldsm2(uint32_t* r, uint32_t addr) {
    asm volatile("ldmatrix.sync.aligned.m8n8.x2.shared.b16 {%0,%1}, [%2];"
                 : "=r"(r[0]), "=r"(r[1]) : "r"(addr));
}

__device__ __forceinline__ void mma_bf16(float* d, const uint32_t* a, const uint32_t* b) {
    asm volatile(
        "mma.sync.aligned.m16n8k16.row.col.f32.bf16.bf16.f32 "
        "{%0,%1,%2,%3}, {%4,%5,%6,%7}, {%8,%9}, {%0,%1,%2,%3};"
        : "+f"(d[0]), "+f"(d[1]), "+f"(d[2]), "+f"(d[3])
        : "r"(a[0]), "r"(a[1]), "r"(a[2]), "r"(a[3]), "r"(b[0]), "r"(b[1]));
}

__device__ __forceinline__ uint32_t bfp(float a, float b) {
    __nv_bfloat162 t = __floats2bfloat162_rn(a, b);
    return *reinterpret_cast<uint32_t*>(&t);
}

// vectorized float2 reduction (sm_90+)
__device__ __forceinline__ void red2(float* addr, float a, float b) {
    asm volatile("red.global.add.v2.f32 [%0], {%1, %2};"
                 :: "l"(addr), "f"(a), "f"(b) : "memory");
}

// ---------------- zero kernels ----------------
__global__ void k_init_small() {
    size_t i0 = (size_t)blockIdx.x * blockDim.x + threadIdx.x;
    size_t stride = (size_t)gridDim.x * blockDim.x;
    float4* m = reinterpret_cast<float4*>(g_msg);
    size_t m4 = (size_t)NLOC * NDIM / 4;
    for (size_t i = i0; i < m4; i += stride) m[i] = make_float4(0.f, 0.f, 0.f, 0.f);
    if (i0 < NLOC) g_ecnt[i0] = 0;
}

__global__ void k_zero_red() {
    size_t i0 = (size_t)blockIdx.x * blockDim.x + threadIdx.x;
    size_t stride = (size_t)gridDim.x * blockDim.x;
    float4* r = reinterpret_cast<float4*>(g_reduced);
    size_t n4 = (size_t)NEDGE * EDIM / 4;
    for (size_t i = i0; i < n4; i += stride) r[i] = make_float4(0.f, 0.f, 0.f, 0.f);
}

// ---------------- CSR build ----------------
__global__ void k_count(const int* __restrict__ n2e) {
    int e = blockIdx.x * blockDim.x + threadIdx.x;
    if (e < NEDGE) atomicAdd(&g_ecnt[n2e[e]], 1);
}

__global__ void k_scan() {
    __shared__ int sh[1024];
    int t = threadIdx.x;
    int c[4];
#pragma unroll
    for (int i = 0; i < 4; i++) c[i] = g_ecnt[t * 4 + i];
    int tot = c[0] + c[1] + c[2] + c[3];
    sh[t] = tot;
    __syncthreads();
    for (int st = 1; st < 1024; st <<= 1) {
        int add = (t >= st) ? sh[t - st] : 0;
        __syncthreads();
        sh[t] += add;
        __syncthreads();
    }
    int run = sh[t] - tot;
#pragma unroll
    for (int i = 0; i < 4; i++) {
        g_eoff[t * 4 + i] = run;
        g_ecur[t * 4 + i] = run;
        run += c[i];
    }
    if (t == 1023) g_eoff[NLOC] = run;
}

__global__ void k_scatter(const int* __restrict__ n2e) {
    int e = blockIdx.x * blockDim.x + threadIdx.x;
    if (e < NEDGE) {
        int n = n2e[e];
        int pos = atomicAdd(&g_ecur[n], 1);
        g_eids[pos] = e;
        g_enode[pos] = n;
    }
}

// ---------------- sym op: 4-way edge parallelism ----------------
__global__ __launch_bounds__(768) void k_sym(
    const float* __restrict__ edge_ebd, const float* __restrict__ node_ext,
    const float* __restrict__ h2, const float* __restrict__ sw,
    const int* __restrict__ n_ext2e) {
    __shared__ float P[4][3][192];
    __shared__ float S0[192], S1[192], S2[192];
    __shared__ float symv[768];
    int n = blockIdx.x;
    int t = threadIdx.x;
    int g = t / 192;
    int f = t - g * 192;
    int beg = g_eoff[n], end = g_eoff[n + 1];
    float a0 = 0.f, a1 = 0.f, a2 = 0.f;
    for (int i = beg + g; i < end; i += 4) {
        int e = g_eids[i];
        float swv = sw[e];
        float h0 = h2[e * 3 + 0] * swv;
        float h1 = h2[e * 3 + 1] * swv;
        float hh = h2[e * 3 + 2] * swv;
        float val = (f < 64) ? edge_ebd[(size_t)e * EDIM + f]
                             : node_ext[(size_t)n_ext2e[e] * NDIM + (f - 64)];
        a0 += h0 * val;
        a1 += h1 * val;
        a2 += hh * val;
    }
    P[g][0][f] = a0; P[g][1][f] = a1; P[g][2][f] = a2;
    __syncthreads();
    if (t < 192) {
        S0[t] = P[0][0][t] + P[1][0][t] + P[2][0][t] + P[3][0][t];
    } else if (t < 384) {
        int tt = t - 192;
        S1[tt] = P[0][1][tt] + P[1][1][tt] + P[2][1][tt] + P[3][1][tt];
    } else if (t < 576) {
        int tt = t - 384;
        S2[tt] = P[0][2][tt] + P[1][2][tt] + P[2][2][tt] + P[3][2][tt];
    }
    __syncthreads();
    if (t < 64) {
#pragma unroll
        for (int a = 0; a < 4; a++)
            symv[a * 64 + t] = SYM_SCALE * (S0[a] * S0[t] + S1[a] * S1[t] + S2[a] * S2[t]);
    } else if (t < 192) {
        int dn = t - 64;
#pragma unroll
        for (int a = 0; a < 4; a++)
            symv[256 + a * 128 + dn] =
                SYM_SCALE * (S0[64 + a] * S0[t] + S1[64 + a] * S1[t] + S2[64 + a] * S2[t]);
    }
    __syncthreads();
    g_sym[(size_t)n * 768 + t] = symv[t];
}

// ---------------- node_sym GEMM fused with node_self (M=32 tiles) ----------------
__global__ __launch_bounds__(256) void k_symmm(
    const float* __restrict__ W_sym, const float* __restrict__ b_sym,
    const float* __restrict__ n_res1,
    const float* __restrict__ W_self, const float* __restrict__ b_self,
    const float* __restrict__ n_res0,
    const float* __restrict__ node_ext, float* __restrict__ out_node) {
    __shared__ float Wt[32 * 128];
    __shared__ float At[32 * 36];
    int tid = threadIdx.x;
    int jt = tid & 31, mt = tid >> 5;
    int n0 = blockIdx.x * 32;
    float acc0[4][4], acc1[4][4];
#pragma unroll
    for (int i = 0; i < 4; i++)
#pragma unroll
        for (int q = 0; q < 4; q++) { acc0[i][q] = 0.f; acc1[i][q] = 0.f; }

    for (int kt = 0; kt < 768; kt += 32) {
        for (int idx = tid; idx < 32 * 128; idx += 256)
            Wt[idx] = W_sym[(size_t)(kt + idx / 128) * 128 + (idx % 128)];
        for (int idx = tid; idx < 32 * 32; idx += 256) {
            int m = idx / 32, k = idx % 32;
            At[k * 36 + m] = g_sym[(size_t)(n0 + m) * 768 + kt + k];
        }
        __syncthreads();
#pragma unroll 4
        for (int k = 0; k < 32; k++) {
            float4 A0 = *reinterpret_cast<const float4*>(&At[k * 36 + mt * 4]);
            float am[4] = {A0.x, A0.y, A0.z, A0.w};
            float4 wv = *reinterpret_cast<const float4*>(&Wt[k * 128 + jt * 4]);
            float wq[4] = {wv.x, wv.y, wv.z, wv.w};
#pragma unroll
            for (int i = 0; i < 4; i++)
#pragma unroll
                for (int q = 0; q < 4; q++) acc0[i][q] += am[i] * wq[q];
        }
        __syncthreads();
    }
    for (int kt = 0; kt < 128; kt += 32) {
        for (int idx = tid; idx < 32 * 128; idx += 256)
            Wt[idx] = W_self[(size_t)(kt + idx / 128) * 128 + (idx % 128)];
        for (int idx = tid; idx < 32 * 32; idx += 256) {
            int m = idx / 32, k = idx % 32;
            At[k * 36 + m] = node_ext[(size_t)(n0 + m) * NDIM + kt + k];
        }
        __syncthreads();
#pragma unroll 4
        for (int k = 0; k < 32; k++) {
            float4 A0 = *reinterpret_cast<const float4*>(&At[k * 36 + mt * 4]);
            float am[4] = {A0.x, A0.y, A0.z, A0.w};
            float4 wv = *reinterpret_cast<const float4*>(&Wt[k * 128 + jt * 4]);
            float wq[4] = {wv.x, wv.y, wv.z, wv.w};
#pragma unroll
            for (int i = 0; i < 4; i++)
#pragma unroll
                for (int q = 0; q < 4; q++) acc1[i][q] += am[i] * wq[q];
        }
        __syncthreads();
    }
#pragma unroll
    for (int i = 0; i < 4; i++) {
        int n = n0 + mt * 4 + i;
#pragma unroll
        for (int q = 0; q < 4; q++) {
            int j = jt * 4 + q;
            float y1 = silu_f(acc0[i][q] + b_sym[j]);
            float y0 = silu_f(acc1[i][q] + b_self[j]);
            out_node[(size_t)n * 128 + j] =
                node_ext[(size_t)n * NDIM + j] + n_res0[j] * y0 + n_res1[j] * y1;
        }
    }
}

// ---------------- fused base/base2 precompute ----------------
__global__ __launch_bounds__(256) void k_bases(const float* __restrict__ node_ext,
                                               const float* __restrict__ W_ne,
                                               const float* __restrict__ W_es,
                                               const float* __restrict__ b_ne,
                                               const float* __restrict__ b_es) {
    __shared__ float Wt[32 * 192];
    __shared__ float At[32 * 72];
    int tid = threadIdx.x;
    int jt = tid & 31, mt = tid >> 5;
    bool role2 = (blockIdx.x >= 64);
    int n0 = (role2 ? (blockIdx.x - 64) : blockIdx.x) * 64;
    int rowbase = role2 ? 128 : 0;
    float acc[8][6];
#pragma unroll
    for (int i = 0; i < 8; i++)
#pragma unroll
        for (int c = 0; c < 6; c++) acc[i][c] = 0.f;
    for (int kt = 0; kt < 128; kt += 32) {
        for (int idx = tid; idx < 32 * 192; idx += 256) {
            int k = idx / 192, j = idx % 192;
            int row = rowbase + kt + k;
            Wt[idx] = (j < 128) ? W_ne[(size_t)row * 128 + j] : W_es[(size_t)row * 64 + (j - 128)];
        }
        for (int idx = tid; idx < 32 * 64; idx += 256) {
            int m = idx / 32, k = idx % 32;
            At[k * 72 + m] = node_ext[(size_t)(n0 + m) * NDIM + kt + k];
        }
        __syncthreads();
#pragma unroll 2
        for (int k = 0; k < 32; k++) {
            float4 A0 = *reinterpret_cast<const float4*>(&At[k * 72 + mt * 8]);
            float4 A1 = *reinterpret_cast<const float4*>(&At[k * 72 + mt * 8 + 4]);
            float am[8] = {A0.x, A0.y, A0.z, A0.w, A1.x, A1.y, A1.z, A1.w};
#pragma unroll
            for (int c = 0; c < 6; c++) {
                float w = Wt[k * 192 + jt + 32 * c];
#pragma unroll
                for (int i = 0; i < 8; i++) acc[i][c] += am[i] * w;
            }
        }
        __syncthreads();
    }
#pragma unroll
    for (int i = 0; i < 8; i++) {
        int n = n0 + mt * 8 + i;
#pragma unroll
        for (int c = 0; c < 6; c++) {
            int j = jt + 32 * c;
            if (role2) {
                g_base2[(size_t)n * 192 + j] = acc[i][c];
            } else {
                float bb = (j < 128) ? b_ne[j] : b_es[j - 128];
                g_base[(size_t)n * 192 + j] = acc[i][c] + bb;
            }
        }
    }
}

// ---------------- nbase precompute (angle kernel, 96 cols) ----------------
__global__ __launch_bounds__(256) void k_nbase(const float* __restrict__ node_ext,
                                               const float* __restrict__ W_ea1,
                                               const float* __restrict__ W_as,
                                               const float* __restrict__ b_ea1,
                                               const float* __restrict__ b_as) {
    __shared__ float Wt[32 * 96];
    __shared__ float At[32 * 72];
    int tid = threadIdx.x;
    int jt = tid & 31, mt = tid >> 5;
    int n0 = blockIdx.x * 64;
    float acc[8][3];
#pragma unroll
    for (int i = 0; i < 8; i++)
#pragma unroll
        for (int c = 0; c < 3; c++) acc[i][c] = 0.f;
    for (int kt = 0; kt < 128; kt += 32) {
        for (int idx = tid; idx < 32 * 96; idx += 256) {
            int k = idx / 96, j = idx % 96;
            int row = 32 + kt + k;
            Wt[idx] = (j < 64) ? W_ea1[(size_t)row * 64 + j] : W_as[(size_t)row * 32 + (j - 64)];
        }
        for (int idx = tid; idx < 32 * 64; idx += 256) {
            int m = idx / 32, k = idx % 32;
            At[k * 72 + m] = node_ext[(size_t)(n0 + m) * NDIM + kt + k];
        }
        __syncthreads();
#pragma unroll 2
        for (int k = 0; k < 32; k++) {
            float4 A0 = *reinterpret_cast<const float4*>(&At[k * 72 + mt * 8]);
            float4 A1 = *reinterpret_cast<const float4*>(&At[k * 72 + mt * 8 + 4]);
            float am[8] = {A0.x, A0.y, A0.z, A0.w, A1.x, A1.y, A1.z, A1.w};
#pragma unroll
            for (int c = 0; c < 3; c++) {
                float w = Wt[k * 96 + jt + 32 * c];
#pragma unroll
                for (int i = 0; i < 8; i++) acc[i][c] += am[i] * w;
            }
        }
        __syncthreads();
    }
#pragma unroll
    for (int i = 0; i < 8; i++) {
        int n = n0 + mt * 8 + i;
#pragma unroll
        for (int c = 0; c < 3; c++) {
            int j = jt + 32 * c;
            float bb = (j < 64) ? b_ea1[j] : b_as[j - 64];
            g_nbase[(size_t)n * 96 + j] = acc[i][c] + bb;
        }
    }
}

// ================= edge GEMM via mma.sync bf16 1-term =================
#define ET_WH 0
#define ET_AH 27648
#define ET_IDX 36864
#define ET_SMEM 37888

__global__ __launch_bounds__(512, 2) void k_edge_tc(
    const float* __restrict__ edge_ebd,
    const float* __restrict__ sw, const int* __restrict__ n_ext2e,
    const float* __restrict__ W_ne, const float* __restrict__ W_es,
    const float* __restrict__ e_res0, float* __restrict__ out_edge) {
    extern __shared__ char smc[];
    uint32_t sb = smem_u32(smc);
    int tid = threadIdx.x;
    int wid = tid >> 5;
    int lane = tid & 31;
    int wm = wid >> 2;
    int wn = wid & 3;

    int* eidv = (int*)(smc + ET_IDX);
    int* nodev = eidv + 64;
    int* neiv = nodev + 64;
    float* sws = (float*)(neiv + 64);

    for (int idx = tid; idx < 192 * 64; idx += 512) {
        int j = idx / 64, k = idx % 64;
        int row = 256 + k;
        float w = (j < 128) ? W_ne[(size_t)row * 128 + j] : W_es[(size_t)row * 64 + (j - 128)];
        *reinterpret_cast<__nv_bfloat16*>(smc + ET_WH + (j * 72 + k) * 2) = __float2bfloat16(w);
    }

    uint32_t aRow = wm * 16 + (lane & 15);
    uint32_t aColH = (lane >> 4);
    uint32_t aAddrH = sb + ET_AH + (aRow * 72 + aColH * 8) * 2;
    int nrow = wn * 48 + (lane & 7) + ((lane & 16) ? 8 : 0);
    int khalf = (lane & 8) ? 8 : 0;
    uint32_t bAddrH = sb + ET_WH + (nrow * 72 + khalf) * 2;

    int mfill = tid & 63;
    int seg = tid >> 6;

    for (int ch = blockIdx.x; ch < NEDGE / 64; ch += gridDim.x) {
        int c0 = ch * 64;
        __syncthreads();
        if (tid < 64) {
            int e = g_eids[c0 + tid];
            eidv[tid] = e;
            nodev[tid] = g_enode[c0 + tid];
            neiv[tid] = n_ext2e[e];
            sws[tid] = sw[e];
        }
        {
            int e = __ldg(&g_eids[c0 + mfill]);
            const float4* erowp = (const float4*)(edge_ebd + (size_t)e * EDIM);
            uint32_t rowoff = (uint32_t)mfill * 72;
#pragma unroll
            for (int q = 0; q < 2; q++) {
                int kk = seg * 8 + q * 4;
                float4 v = erowp[kk >> 2];
                uint32_t hi01 = bfp(v.x, v.y);
                uint32_t hi23 = bfp(v.z, v.w);
                uint32_t boff = (rowoff + kk) * 2;
                *reinterpret_cast<uint32_t*>(smc + ET_AH + boff) = hi01;
                *reinterpret_cast<uint32_t*>(smc + ET_AH + boff + 4) = hi23;
            }
        }
        __syncthreads();

        float d[6][4];
#pragma unroll
        for (int nt = 0; nt < 6; nt++)
#pragma unroll
            for (int q = 0; q < 4; q++) d[nt][q] = 0.f;

#pragma unroll
        for (int s = 0; s < 4; s++) {
            uint32_t ah[4];
            ldsm4(ah, aAddrH + s * 32);
#pragma unroll
            for (int pr = 0; pr < 3; pr++) {
                uint32_t bh[4];
                ldsm4(bh, bAddrH + pr * 16 * 144 + s * 32);
                mma_bf16(d[pr * 2], ah, bh);
                mma_bf16(d[pr * 2 + 1], ah, bh + 2);
            }
        }

        int g = lane >> 2, qt = lane & 3;
        int r0 = wm * 16 + g, r1 = r0 + 8;
        int nd0 = nodev[r0], nd1 = nodev[r1];
        int ne0 = neiv[r0], ne1 = neiv[r1];
        float sw0 = sws[r0], sw1 = sws[r1];
        int ee0 = eidv[r0], ee1 = eidv[r1];
        bool samend = (nd0 == nd1);
#pragma unroll
        for (int nt = 0; nt < 6; nt++) {
            int j0 = wn * 48 + nt * 8 + qt * 2;
            float2 b0v = *(const float2*)(g_base + (size_t)nd0 * 192 + j0);
            float2 b1v = *(const float2*)(g_base + (size_t)nd1 * 192 + j0);
            float2 c0v = *(const float2*)(g_base2 + (size_t)ne0 * 192 + j0);
            float2 c1v = *(const float2*)(g_base2 + (size_t)ne1 * 192 + j0);
            float y00 = silu_f(d[nt][0] + b0v.x + c0v.x);
            float y01 = silu_f(d[nt][1] + b0v.y + c0v.y);
            float y10 = silu_f(d[nt][2] + b1v.x + c1v.x);
            float y11 = silu_f(d[nt][3] + b1v.y + c1v.y);
            if (j0 < 128) {
                float v00 = y00 * sw0, v01 = y01 * sw0;
                float v10 = y10 * sw1, v11 = y11 * sw1;
                if (samend) {
                    red2(&g_msg[(size_t)nd0 * NDIM + j0], v00 + v10, v01 + v11);
                } else {
                    red2(&g_msg[(size_t)nd0 * NDIM + j0], v00, v01);
                    red2(&g_msg[(size_t)nd1 * NDIM + j0], v10, v11);
                }
            } else {
                int col = j0 - 128;
                float2 er = *(const float2*)(e_res0 + col);
                size_t o0 = (size_t)ee0 * EDIM + col;
                size_t o1 = (size_t)ee1 * EDIM + col;
                float2 eb0 = *(const float2*)(edge_ebd + o0);
                float2 eb1 = *(const float2*)(edge_ebd + o1);
                *(float2*)(out_edge + o0) = make_float2(eb0.x + er.x * y00, eb0.y + er.y * y01);
                *(float2*)(out_edge + o1) = make_float2(eb1.x + er.x * y10, eb1.y + er.y * y11);
            }
        }
    }
}

// ================= angle GEMM via mma.sync bf16 1-term =================
#define AT_WH 0
#define AT_AH 32256
#define AT_IDX 53760
#define AT_SMEM 54528

__global__ __launch_bounds__(512, 2) void k_angle_tc(
    const float* __restrict__ angle_ebd, const float* __restrict__ edge_ebd,
    const int* __restrict__ ai, const float* __restrict__ a_sw,
    const float* __restrict__ W_ea1, const float* __restrict__ W_as,
    const float* __restrict__ a_res0, float* __restrict__ out_angle) {
    extern __shared__ char smc[];
    uint32_t sb = smem_u32(smc);
    int tid = threadIdx.x;
    int wid = tid >> 5;
    int lane = tid & 31;
    int wm = wid >> 2;
    int wn = wid & 3;

    int* nav = (int*)(smc + AT_IDX);
    int* ijav = nav + 64;
    float* aswv = (float*)(ijav + 64);

    const int* n2a = ai;
    const int* eij = ai + NANGLE;
    const int* eik = ai + 2 * NANGLE;

    for (int idx = tid; idx < 96 * 160; idx += 512) {
        int j = idx / 160, k = idx % 160;
        int srck = (k < 32) ? k : ((k < 96) ? 160 + (k - 32) : 224 + (k - 96));
        float w = (j < 64) ? W_ea1[(size_t)srck * 64 + j] : W_as[(size_t)srck * 32 + (j - 64)];
        *reinterpret_cast<__nv_bfloat16*>(smc + AT_WH + (j * 168 + k) * 2) = __float2bfloat16(w);
    }

    uint32_t aRow = wm * 16 + (lane & 15);
    uint32_t aColH = (lane >> 4);
    uint32_t aAddrH = sb + AT_AH + (aRow * 168 + aColH * 8) * 2;
    int nrow = wn * 24 + (lane & 7) + ((lane & 16) ? 8 : 0);
    int khalf = (lane & 8) ? 8 : 0;
    uint32_t bAddrH = sb + AT_WH + (nrow * 168 + khalf) * 2;
    int nrow2 = wn * 24 + 16 + (lane & 7);
    int khalf2 = (lane & 8) ? 8 : 0;
    uint32_t b2AddrH = sb + AT_WH + (nrow2 * 168 + khalf2) * 2;

    int mfill = tid & 63;
    int seg = tid >> 6;

    for (int t = blockIdx.x; t < NANGLE / 64; t += gridDim.x) {
        int a0 = t * 64;
        __syncthreads();
        if (tid < 64) {
            nav[tid] = n2a[a0 + tid];
            ijav[tid] = eij[a0 + tid];
            aswv[tid] = a_sw[a0 + tid];
        }
        {
            int a = a0 + mfill;
            int ek = __ldg(&eik[a]);
            int ej = __ldg(&eij[a]);
            const float4* arow = (const float4*)(angle_ebd + (size_t)a * ADIM);
            const float4* krow = (const float4*)(edge_ebd + (size_t)ek * EDIM);
            const float4* jrow = (const float4*)(edge_ebd + (size_t)ej * EDIM);
            uint32_t rowoff = (uint32_t)mfill * 168;
#pragma unroll
            for (int q = 0; q < 5; q++) {
                int kk = seg * 20 + q * 4;
                float4 v = (kk < 32) ? arow[kk >> 2]
                         : (kk < 96) ? krow[(kk - 32) >> 2]
                                     : jrow[(kk - 96) >> 2];
                uint32_t hi01 = bfp(v.x, v.y);
                uint32_t hi23 = bfp(v.z, v.w);
                uint32_t boff = (rowoff + kk) * 2;
                *reinterpret_cast<uint32_t*>(smc + AT_AH + boff) = hi01;
                *reinterpret_cast<uint32_t*>(smc + AT_AH + boff + 4) = hi23;
            }
        }
        __syncthreads();

        float d[3][4];
#pragma unroll
        for (int nt = 0; nt < 3; nt++)
#pragma unroll
            for (int q = 0; q < 4; q++) d[nt][q] = 0.f;

#pragma unroll
        for (int s = 0; s < 10; s++) {
            uint32_t ah[4];
            ldsm4(ah, aAddrH + s * 32);
            uint32_t bh[4], b2h[2];
            ldsm4(bh, bAddrH + s * 32);
            ldsm2(b2h, b2AddrH + s * 32);
            mma_bf16(d[0], ah, bh);
            mma_bf16(d[1], ah, bh + 2);
            mma_bf16(d[2], ah, b2h);
        }

        int g = lane >> 2, qt = lane & 3;
        int r0 = wm * 16 + g, r1 = r0 + 8;
        int nd0 = nav[r0], nd1 = nav[r1];
        float sw0 = aswv[r0], sw1 = aswv[r1];
        int ij0 = ijav[r0], ij1 = ijav[r1];
#pragma unroll
        for (int nt = 0; nt < 3; nt++) {
            int j0 = wn * 24 + nt * 8 + qt * 2;
            float2 nb0 = *(const float2*)(g_nbase + (size_t)nd0 * 96 + j0);
            float2 nb1 = *(const float2*)(g_nbase + (size_t)nd1 * 96 + j0);
            float y00 = silu_f(d[nt][0] + nb0.x);
            float y01 = silu_f(d[nt][1] + nb0.y);
            float y10 = silu_f(d[nt][2] + nb1.x);
            float y11 = silu_f(d[nt][3] + nb1.y);
            if (j0 < 64) {
                red2(&g_reduced[(size_t)ij0 * EDIM + j0], y00 * sw0, y01 * sw0);
                red2(&g_reduced[(size_t)ij1 * EDIM + j0], y10 * sw1, y11 * sw1);
            } else {
                int col = j0 - 64;
                float2 arr = *(const float2*)(a_res0 + col);
                size_t o0 = (size_t)(a0 + r0) * ADIM + col;
                size_t o1 = (size_t)(a0 + r1) * ADIM + col;
                float2 ae0 = *(const float2*)(angle_ebd + o0);
                float2 ae1 = *(const float2*)(angle_ebd + o1);
                *(float2*)(out_angle + o0) = make_float2(ae0.x + arr.x * y00, ae0.y + arr.y * y01);
                *(float2*)(out_angle + o1) = make_float2(ae1.x + arr.x * y10, ae1.y + arr.y * y11);
            }
        }
    }
}

// ================= edge angle message GEMM (+ node finish blocks) =================
__global__ __launch_bounds__(256) void k_edge_msg(const float* __restrict__ W2,
                                                  const float* __restrict__ b2,
                                                  const float* __restrict__ e_res1,
                                                  float* __restrict__ out_edge,
                                                  const float* __restrict__ n_res2,
                                                  float* __restrict__ out_node) {
    int tid = threadIdx.x;
    if (blockIdx.x >= NEDGE / 64) {
        int i0 = (blockIdx.x - NEDGE / 64) * 256 + tid;
        for (int i = i0; i < NLOC * NDIM; i += 64 * 256) {
            int j = i & (NDIM - 1);
            out_node[i] += n_res2[j] * g_msg[i] * INV_DYN_E;
        }
        return;
    }
    __shared__ __align__(16) __nv_bfloat16 Wh[64 * 72];
    __shared__ __align__(16) __nv_bfloat16 Ah[64 * 72];
    int wid = tid >> 5;
    int lane = tid & 31;
    int wm = wid >> 1;
    int wn = wid & 1;
    int e0 = blockIdx.x * 64;

    for (int idx = tid; idx < 64 * 64; idx += 256) {
        int j = idx >> 6, k = idx & 63;
        Wh[j * 72 + k] = __float2bfloat16(W2[k * 64 + j]);
    }
    {
        int m = tid & 63, seg = tid >> 6;
        const float4* src = (const float4*)(g_reduced + (size_t)(e0 + m) * EDIM + seg * 16);
#pragma unroll
        for (int q = 0; q < 4; q++) {
            float4 v = src[q];
            int kk = seg * 16 + q * 4;
            Ah[m * 72 + kk + 0] = __float2bfloat16(v.x);
            Ah[m * 72 + kk + 1] = __float2bfloat16(v.y);
            Ah[m * 72 + kk + 2] = __float2bfloat16(v.z);
            Ah[m * 72 + kk + 3] = __float2bfloat16(v.w);
        }
    }
    __syncthreads();

    uint32_t aRow = wm * 16 + (lane & 15);
    uint32_t aColH = (lane >> 4);
    uint32_t aAddrH = smem_u32(Ah) + (aRow * 72 + aColH * 8) * 2;
    int nrow = wn * 32 + (lane & 7) + ((lane & 16) ? 8 : 0);
    int khalf = (lane & 8) ? 8 : 0;
    uint32_t bAddrH = smem_u32(Wh) + (nrow * 72 + khalf) * 2;
    uint32_t b2AddrH = bAddrH + 16 * 144;

    float d[4][4];
#pragma unroll
    for (int nt = 0; nt < 4; nt++)
#pragma unroll
        for (int q = 0; q < 4; q++) d[nt][q] = 0.f;

#pragma unroll
    for (int s = 0; s < 4; s++) {
        uint32_t ah[4];
        ldsm4(ah, aAddrH + s * 32);
        uint32_t bh[4], ch[4];
        ldsm4(bh, bAddrH + s * 32);
        ldsm4(ch, b2AddrH + s * 32);
        mma_bf16(d[0], ah, bh);
        mma_bf16(d[1], ah, bh + 2);
        mma_bf16(d[2], ah, ch);
        mma_bf16(d[3], ah, ch + 2);
    }

    int g = lane >> 2, qt = lane & 3;
    int r0 = wm * 16 + g, r1 = r0 + 8;
#pragma unroll
    for (int nt = 0; nt < 4; nt++) {
        int j0 = wn * 32 + nt * 8 + qt * 2;
        float2 bb = *(const float2*)(b2 + j0);
        float2 er = *(const float2*)(e_res1 + j0);
        size_t o0 = (size_t)(e0 + r0) * EDIM + j0;
        size_t o1 = (size_t)(e0 + r1) * EDIM + j0;
        float2 v0 = *(float2*)(out_edge + o0);
        float2 v1 = *(float2*)(out_edge + o1);
        v0.x += er.x * silu_f(d[nt][0] + bb.x);
        v0.y += er.y * silu_f(d[nt][1] + bb.y);
        v1.x += er.x * silu_f(d[nt][2] + bb.x);
        v1.y += er.y * silu_f(d[nt][3] + bb.y);
        *(float2*)(out_edge + o0) = v0;
        *(float2*)(out_edge + o1) = v1;
    }
}

// ---------------- launch ----------------
extern "C" void kernel_launch(void* const* d_in, const int* in_sizes, int n_in,
                              void* d_out, int out_size) {
    const float* node_ext   = (const float*)d_in[0];
    const float* edge_ebd   = (const float*)d_in[1];
    const float* h2         = (const float*)d_in[2];
    const float* angle_ebd  = (const float*)d_in[3];
    const float* sw         = (const float*)d_in[6];
    const float* a_sw       = (const float*)d_in[9];
    const int*   edge_index = (const int*)d_in[10];
    const int*   angle_index= (const int*)d_in[11];
    const float* W_node_self = (const float*)d_in[12];
    const float* b_node_self = (const float*)d_in[13];
    const float* W_node_sym  = (const float*)d_in[14];
    const float* b_node_sym  = (const float*)d_in[15];
    const float* W_node_edge = (const float*)d_in[16];
    const float* b_node_edge = (const float*)d_in[17];
    const float* W_edge_self = (const float*)d_in[18];
    const float* b_edge_self = (const float*)d_in[19];
    const float* W_edge_angle1 = (const float*)d_in[20];
    const float* b_edge_angle1 = (const float*)d_in[21];
    const float* W_edge_angle2 = (const float*)d_in[22];
    const float* b_edge_angle2 = (const float*)d_in[23];
    const float* W_angle_self  = (const float*)d_in[24];
    const float* b_angle_self  = (const float*)d_in[25];
    const float* n_res0 = (const float*)d_in[26];
    const float* n_res1 = (const float*)d_in[27];
    const float* n_res2 = (const float*)d_in[28];
    const float* e_res0 = (const float*)d_in[29];
    const float* e_res1 = (const float*)d_in[30];
    const float* a_res0 = (const float*)d_in[31];

    float* out = (float*)d_out;
    float* out_node  = out;
    float* out_edge  = out + (size_t)NLOC * NDIM;
    float* out_angle = out_edge + (size_t)NEDGE * EDIM;

    const int* n2e = edge_index;
    const int* n_ext2e = edge_index + NEDGE;

    cudaFuncSetAttribute((const void*)k_edge_tc,
                         cudaFuncAttributeMaxDynamicSharedMemorySize, ET_SMEM);
    cudaFuncSetAttribute((const void*)k_angle_tc,
                         cudaFuncAttributeMaxDynamicSharedMemorySize, AT_SMEM);

    k_init_small<<<2048, 256>>>();
    k_zero_red<<<4096, 256>>>();
    k_count<<<NEDGE / 256, 256>>>(n2e);
    k_scan<<<1, 1024>>>();
    k_scatter<<<NEDGE / 256, 256>>>(n2e);
    k_sym<<<NLOC, 768>>>(edge_ebd, node_ext, h2, sw, n_ext2e);
    k_symmm<<<NLOC / 32, 256>>>(W_node_sym, b_node_sym, n_res1,
                                W_node_self, b_node_self, n_res0, node_ext, out_node);
    k_bases<<<160, 256>>>(node_ext, W_node_edge, W_edge_self, b_node_edge, b_edge_self);
    k_nbase<<<NLOC / 64, 256>>>(node_ext, W_edge_angle1, W_angle_self,
                                b_edge_angle1, b_angle_self);
    k_edge_tc<<<296, 512, ET_SMEM>>>(edge_ebd, sw, n_ext2e,
                                     W_node_edge, W_edge_self, e_res0, out_edge);
    k_angle_tc<<<296, 512, AT_SMEM>>>(angle_ebd, edge_ebd, angle_index, a_sw,
                                      W_edge_angle1, W_angle_self, a_res0, out_angle);
    k_edge_msg<<<NEDGE / 64 + 64, 256>>>(W_edge_angle2, b_edge_angle2, e_res1, out_edge,
                                         n_res2, out_node);
}